// round 2
// baseline (speedup 1.0000x reference)
#include <cuda_runtime.h>

#define DD   256
#define BB   4
#define LXN  512
#define LMN  512

#define TXK  32     // x-rows per attn tile
#define TMK  64     // m-cols per attn tile
#define S1_LD 34    // padded leading dim for s1 (float2-aligned, conflict-free)
#define S2_LD 68    // padded leading dim for s2 (float4-aligned, conflict-free)

// scratch for precomputed projections (no cudaMalloc allowed)
__device__ float g_item1[BB * LXN * DD];
__device__ float g_item2[BB * LMN * DD];

__device__ __forceinline__ float fast_tanh(float x) {
    float y;
    asm("tanh.approx.f32 %0, %1;" : "=f"(y) : "f"(x));
    return y;
}

// ---------------------------------------------------------------------------
// NT-GEMM: out[r][n] = sum_k A[r][k] * W[n][k] (+ bias[n])
// rows = 2048, N = K = 256. Tile 64x64, BK=16, 256 threads, 4x4 microtile.
// which==0 -> g_item1 (with bias), which==1 -> g_item2 (no bias)
// ---------------------------------------------------------------------------
__global__ __launch_bounds__(256) void gemm_nt(const float* __restrict__ A,
                                               const float* __restrict__ W,
                                               const float* __restrict__ bias,
                                               int which) {
    __shared__ float As[16][68];
    __shared__ float Ws[16][68];

    float* out = which ? g_item2 : g_item1;

    const int tid = threadIdx.x;
    const int m0 = blockIdx.x * 64;
    const int n0 = blockIdx.y * 64;
    const int tx = tid & 15;        // 16 thread cols -> m microtiles
    const int ty = tid >> 4;        // 16 thread rows -> n microtiles
    const int lr = tid >> 2;        // load row 0..63
    const int lk = (tid & 3) << 2;  // load k offset {0,4,8,12}

    float acc[4][4] = {};

    for (int k0 = 0; k0 < DD; k0 += 16) {
        float4 av = *(const float4*)&A[(m0 + lr) * DD + k0 + lk];
        float4 wv = *(const float4*)&W[(n0 + lr) * DD + k0 + lk];
        __syncthreads();
        As[lk + 0][lr] = av.x; As[lk + 1][lr] = av.y;
        As[lk + 2][lr] = av.z; As[lk + 3][lr] = av.w;
        Ws[lk + 0][lr] = wv.x; Ws[lk + 1][lr] = wv.y;
        Ws[lk + 2][lr] = wv.z; Ws[lk + 3][lr] = wv.w;
        __syncthreads();

        #pragma unroll
        for (int k = 0; k < 16; ++k) {
            float4 a4 = *(const float4*)&As[k][tx * 4];
            float4 w4 = *(const float4*)&Ws[k][ty * 4];
            float ar[4] = {a4.x, a4.y, a4.z, a4.w};
            float wr[4] = {w4.x, w4.y, w4.z, w4.w};
            #pragma unroll
            for (int i = 0; i < 4; ++i)
                #pragma unroll
                for (int j = 0; j < 4; ++j)
                    acc[i][j] += ar[i] * wr[j];
        }
    }

    float4 bv = make_float4(0.f, 0.f, 0.f, 0.f);
    if (bias) bv = *(const float4*)&bias[n0 + ty * 4];

    #pragma unroll
    for (int i = 0; i < 4; ++i) {
        int r = m0 + tx * 4 + i;
        float4 v;
        v.x = acc[i][0] + bv.x;
        v.y = acc[i][1] + bv.y;
        v.z = acc[i][2] + bv.z;
        v.w = acc[i][3] + bv.w;
        *(float4*)&out[r * DD + n0 + ty * 4] = v;
    }
}

// ---------------------------------------------------------------------------
// Main: S[b,x,m] = sum_d tanh(item1[b,x,d] + item2[b,m,d]) * Wt[d], masked.
// Tile: 32 x-rows x 64 m-cols per CTA. smem holds both tiles TRANSPOSED
// ([d][row] layout) so the inner loop reads contiguous float2/float4.
// Each thread: 2x4 microtile -> 8 independent tanh per d (hides MUFU lat).
// ---------------------------------------------------------------------------
extern __shared__ float smem_dyn[];

__global__ __launch_bounds__(256) void attn_kernel(const int* __restrict__ mask,
                                                   const float* __restrict__ Wt,
                                                   float* __restrict__ out) {
    float* s1   = smem_dyn;                       // [DD][S1_LD]
    float* s2   = smem_dyn + DD * S1_LD;          // [DD][S2_LD]
    float* swt  = s2 + DD * S2_LD;                // [DD]
    int*   smsk = (int*)(swt + DD);               // [TMK]

    const int tid = threadIdx.x;
    const int b  = blockIdx.z;
    const int x0 = blockIdx.x * TXK;
    const int m0 = blockIdx.y * TMK;

    const float* p1 = g_item1 + (b * LXN + x0) * DD;
    const float* p2 = g_item2 + (b * LMN + m0) * DD;

    // --- load s1 (32 rows x 256 d), transposed. Conflict-free STS:
    // lane = row, warp owns a 32-wide d-block.
    {
        int row = tid & 31;
        int d0  = (tid >> 5) << 5;
        #pragma unroll
        for (int j = 0; j < 8; ++j) {
            int d = d0 + j * 4;
            float4 v = *(const float4*)&p1[row * DD + d];
            s1[(d + 0) * S1_LD + row] = v.x;
            s1[(d + 1) * S1_LD + row] = v.y;
            s1[(d + 2) * S1_LD + row] = v.z;
            s1[(d + 3) * S1_LD + row] = v.w;
        }
        // --- load s2 (64 rows x 256 d), transposed
        #pragma unroll
        for (int rr = 0; rr < 2; ++rr) {
            int r = row + rr * 32;
            #pragma unroll
            for (int j = 0; j < 8; ++j) {
                int d = d0 + j * 4;
                float4 v = *(const float4*)&p2[r * DD + d];
                s2[(d + 0) * S2_LD + r] = v.x;
                s2[(d + 1) * S2_LD + r] = v.y;
                s2[(d + 2) * S2_LD + r] = v.z;
                s2[(d + 3) * S2_LD + r] = v.w;
            }
        }
    }
    if (tid < DD)  swt[tid]  = Wt[tid];
    if (tid < TMK) smsk[tid] = mask[b * LMN + m0 + tid];
    __syncthreads();

    const int tx = tid & 15;   // x microtile (2 rows)
    const int tm = tid >> 4;   // m microtile (4 cols)

    const float* s1p = s1 + tx * 2;
    const float* s2p = s2 + tm * 4;

    float acc[2][4] = {};

    #pragma unroll 4
    for (int d = 0; d < DD; ++d) {
        float  wt = swt[d];
        float2 a  = *(const float2*)&s1p[d * S1_LD];
        float4 m4 = *(const float4*)&s2p[d * S2_LD];

        acc[0][0] += fast_tanh(a.x + m4.x) * wt;
        acc[0][1] += fast_tanh(a.x + m4.y) * wt;
        acc[0][2] += fast_tanh(a.x + m4.z) * wt;
        acc[0][3] += fast_tanh(a.x + m4.w) * wt;
        acc[1][0] += fast_tanh(a.y + m4.x) * wt;
        acc[1][1] += fast_tanh(a.y + m4.y) * wt;
        acc[1][2] += fast_tanh(a.y + m4.z) * wt;
        acc[1][3] += fast_tanh(a.y + m4.w) * wt;
    }

    int mk[4];
    #pragma unroll
    for (int j = 0; j < 4; ++j) mk[j] = smsk[tm * 4 + j];

    #pragma unroll
    for (int i = 0; i < 2; ++i) {
        int x = x0 + tx * 2 + i;
        float4 v;
        v.x = mk[0] ? acc[i][0] : -10000.0f;
        v.y = mk[1] ? acc[i][1] : -10000.0f;
        v.z = mk[2] ? acc[i][2] : -10000.0f;
        v.w = mk[3] ? acc[i][3] : -10000.0f;
        *(float4*)&out[((b * LXN + x) * (long)LMN) + m0 + tm * 4] = v;
    }
}

// ---------------------------------------------------------------------------

extern "C" void kernel_launch(void* const* d_in, const int* in_sizes, int n_in,
                              void* d_out, int out_size) {
    const float* x      = (const float*)d_in[0];
    const float* memory = (const float*)d_in[1];
    const int*   mask   = (const int*)d_in[2];
    const float* W1     = (const float*)d_in[3];
    const float* b1     = (const float*)d_in[4];
    const float* W2     = (const float*)d_in[5];
    const float* Wt     = (const float*)d_in[6];
    float* out = (float*)d_out;

    // projections: rows = B*L = 2048 each, tiles 64x64 -> grid (32, 4)
    dim3 ggrid(2048 / 64, DD / 64);
    gemm_nt<<<ggrid, 256>>>(x,      W1, b1,      0);
    gemm_nt<<<ggrid, 256>>>(memory, W2, nullptr, 1);

    const int smem_bytes = (DD * S1_LD + DD * S2_LD + DD) * 4 + TMK * 4;
    cudaFuncSetAttribute(attn_kernel,
                         cudaFuncAttributeMaxDynamicSharedMemorySize, smem_bytes);
    dim3 agrid(LXN / TXK, LMN / TMK, BB);
    attn_kernel<<<agrid, 256, smem_bytes>>>(mask, Wt, out);
}

// round 3
// speedup vs baseline: 1.1946x; 1.1946x over previous
#include <cuda_runtime.h>
#include <cuda_fp16.h>

#define DD   256
#define BB   4
#define LXN  512
#define LMN  512

#define TXK  32      // x-rows per attn tile
#define TMK  64      // m-cols per attn tile
#define S1H_LD 40    // halves; 80B rows (16B aligned)
#define S2H_LD 72    // halves; 144B rows (16B aligned)

// Transposed half projections: [b][d][L]
__device__ __half g_item1t[BB * DD * LXN];
__device__ __half g_item2t[BB * DD * LMN];

__device__ __forceinline__ __half2 htanh2(__half2 x) {
    unsigned u = *reinterpret_cast<unsigned*>(&x);
    unsigned r;
    asm("tanh.approx.f16x2 %0, %1;" : "=r"(r) : "r"(u));
    return *reinterpret_cast<__half2*>(&r);
}

// ---------------------------------------------------------------------------
// Fused NT-GEMM pair: out_t[b][d][l] = half( sum_k A[b,l,k]*W[d,k] (+ bias[d]) )
// blockIdx.z selects (x,W1,+b1) -> g_item1t  or  (memory,W2) -> g_item2t.
// rows = 2048, N = K = 256. Tile 64x64, BK=16, 256 threads, 4x4 microtile.
// Epilogue writes HALF, TRANSPOSED (d-major), so attn does no transpose.
// ---------------------------------------------------------------------------
__global__ __launch_bounds__(256) void gemm_nt_t(const float* __restrict__ Xin,
                                                 const float* __restrict__ Min,
                                                 const float* __restrict__ W1,
                                                 const float* __restrict__ W2,
                                                 const float* __restrict__ b1) {
    __shared__ float As[16][68];
    __shared__ float Ws[16][68];

    const int which = blockIdx.z;
    const float* A = which ? Min : Xin;
    const float* W = which ? W2  : W1;
    __half* out    = which ? g_item2t : g_item1t;

    const int tid = threadIdx.x;
    const int m0 = blockIdx.x * 64;     // row tile (b*L + l)
    const int n0 = blockIdx.y * 64;     // d tile
    const int tx = tid & 15;
    const int ty = tid >> 4;
    const int lr = tid >> 2;
    const int lk = (tid & 3) << 2;

    float acc[4][4] = {};

    for (int k0 = 0; k0 < DD; k0 += 16) {
        float4 av = *(const float4*)&A[(m0 + lr) * DD + k0 + lk];
        float4 wv = *(const float4*)&W[(n0 + lr) * DD + k0 + lk];
        __syncthreads();
        As[lk + 0][lr] = av.x; As[lk + 1][lr] = av.y;
        As[lk + 2][lr] = av.z; As[lk + 3][lr] = av.w;
        Ws[lk + 0][lr] = wv.x; Ws[lk + 1][lr] = wv.y;
        Ws[lk + 2][lr] = wv.z; Ws[lk + 3][lr] = wv.w;
        __syncthreads();

        #pragma unroll
        for (int k = 0; k < 16; ++k) {
            float4 a4 = *(const float4*)&As[k][tx * 4];
            float4 w4 = *(const float4*)&Ws[k][ty * 4];
            float ar[4] = {a4.x, a4.y, a4.z, a4.w};
            float wr[4] = {w4.x, w4.y, w4.z, w4.w};
            #pragma unroll
            for (int i = 0; i < 4; ++i)
                #pragma unroll
                for (int j = 0; j < 4; ++j)
                    acc[i][j] += ar[i] * wr[j];
        }
    }

    // epilogue: transposed half store. 4 consecutive rows share b.
    const int r_base = m0 + tx * 4;
    const int bb = r_base >> 9;          // row / 512
    const int lb = r_base & 511;

    float4 bv = make_float4(0.f, 0.f, 0.f, 0.f);
    if (!which) bv = *(const float4*)&b1[n0 + ty * 4];
    float bj[4] = {bv.x, bv.y, bv.z, bv.w};

    #pragma unroll
    for (int j = 0; j < 4; ++j) {
        int d = n0 + ty * 4 + j;
        __half h0 = __float2half_rn(acc[0][j] + bj[j]);
        __half h1 = __float2half_rn(acc[1][j] + bj[j]);
        __half h2 = __float2half_rn(acc[2][j] + bj[j]);
        __half h3 = __float2half_rn(acc[3][j] + bj[j]);
        __half2 p0 = __halves2half2(h0, h1);
        __half2 p1 = __halves2half2(h2, h3);
        uint2 u;
        u.x = *reinterpret_cast<unsigned*>(&p0);
        u.y = *reinterpret_cast<unsigned*>(&p1);
        *(uint2*)&out[((bb * DD + d) * 512) + lb] = u;   // 8B store
    }
}

// ---------------------------------------------------------------------------
// attn: S[b,x,m] = sum_d tanh(item1[b,x,d]+item2[b,m,d])*Wt[d], masked.
// f16x2 math: 2 elements per HADD2/MUFU.TANH/HFMA2. Tile 32x x 64m, 256 thr,
// each thread a 2x (x) by 2-half2 (m) microtile. fp32 re-accumulate every 64 d.
// ---------------------------------------------------------------------------
extern __shared__ __align__(16) char smem_raw[];

__global__ __launch_bounds__(256) void attn_kernel(const int* __restrict__ mask,
                                                   const float* __restrict__ Wt,
                                                   float* __restrict__ out) {
    __half*   s1   = (__half*)smem_raw;               // [DD][S1H_LD]
    __half*   s2   = s1 + DD * S1H_LD;                // [DD][S2H_LD]
    unsigned* swt  = (unsigned*)(s2 + DD * S2H_LD);   // [DD] half2 splat
    int*      smsk = (int*)(swt + DD);                // [TMK]

    const int tid = threadIdx.x;
    const int b  = blockIdx.z;
    const int x0 = blockIdx.x * TXK;
    const int m0 = blockIdx.y * TMK;

    // --- bulk copy (already d-major half): thread tid owns d-row tid
    {
        const int d = tid;
        const float4* p1 = (const float4*)(g_item1t + (b * DD + d) * LXN + x0);
        float4* q1 = (float4*)(s1 + d * S1H_LD);
        #pragma unroll
        for (int j = 0; j < 4; ++j) q1[j] = p1[j];           // 32 halves
        const float4* p2 = (const float4*)(g_item2t + (b * DD + d) * LMN + m0);
        float4* q2 = (float4*)(s2 + d * S2H_LD);
        #pragma unroll
        for (int j = 0; j < 8; ++j) q2[j] = p2[j];           // 64 halves
        __half h = __float2half_rn(Wt[d]);
        __half2 hh = __halves2half2(h, h);
        swt[d] = *reinterpret_cast<unsigned*>(&hh);
    }
    if (tid < TMK) smsk[tid] = mask[b * LMN + m0 + tid];
    __syncthreads();

    const int tx = tid & 15;    // x pair
    const int tm = tid >> 4;    // m quad
    const __half* s1p = s1 + tx * 2;
    const __half* s2p = s2 + tm * 4;

    const __half2 hz = __halves2half2(__ushort_as_half(0), __ushort_as_half(0));
    float2 f00 = {0.f, 0.f}, f01 = {0.f, 0.f}, f10 = {0.f, 0.f}, f11 = {0.f, 0.f};

    #pragma unroll 1
    for (int d0 = 0; d0 < DD; d0 += 64) {
        __half2 a00 = hz, a01 = hz, a10 = hz, a11 = hz;
        #pragma unroll 8
        for (int d = d0; d < d0 + 64; ++d) {
            __half2 a = *(const __half2*)(s1p + d * S1H_LD);      // 2 x-vals
            uint2 mv  = *(const uint2*)(s2p + d * S2H_LD);        // 4 m-vals
            __half2 m01 = *reinterpret_cast<__half2*>(&mv.x);
            __half2 m23 = *reinterpret_cast<__half2*>(&mv.y);
            unsigned wu = swt[d];
            __half2 wt2 = *reinterpret_cast<__half2*>(&wu);
            __half2 aa0 = __low2half2(a);
            __half2 aa1 = __high2half2(a);
            a00 = __hfma2(htanh2(__hadd2(aa0, m01)), wt2, a00);
            a01 = __hfma2(htanh2(__hadd2(aa0, m23)), wt2, a01);
            a10 = __hfma2(htanh2(__hadd2(aa1, m01)), wt2, a10);
            a11 = __hfma2(htanh2(__hadd2(aa1, m23)), wt2, a11);
        }
        float2 t;
        t = __half22float2(a00); f00.x += t.x; f00.y += t.y;
        t = __half22float2(a01); f01.x += t.x; f01.y += t.y;
        t = __half22float2(a10); f10.x += t.x; f10.y += t.y;
        t = __half22float2(a11); f11.x += t.x; f11.y += t.y;
    }

    int mk0 = smsk[tm * 4 + 0], mk1 = smsk[tm * 4 + 1];
    int mk2 = smsk[tm * 4 + 2], mk3 = smsk[tm * 4 + 3];

    {
        int x = x0 + tx * 2;
        float4 v;
        v.x = mk0 ? f00.x : -10000.0f;
        v.y = mk1 ? f00.y : -10000.0f;
        v.z = mk2 ? f01.x : -10000.0f;
        v.w = mk3 ? f01.y : -10000.0f;
        *(float4*)&out[((b * LXN + x) * (long)LMN) + m0 + tm * 4] = v;
        v.x = mk0 ? f10.x : -10000.0f;
        v.y = mk1 ? f10.y : -10000.0f;
        v.z = mk2 ? f11.x : -10000.0f;
        v.w = mk3 ? f11.y : -10000.0f;
        *(float4*)&out[((b * LXN + x + 1) * (long)LMN) + m0 + tm * 4] = v;
    }
}

// ---------------------------------------------------------------------------

extern "C" void kernel_launch(void* const* d_in, const int* in_sizes, int n_in,
                              void* d_out, int out_size) {
    const float* x      = (const float*)d_in[0];
    const float* memory = (const float*)d_in[1];
    const int*   mask   = (const int*)d_in[2];
    const float* W1     = (const float*)d_in[3];
    const float* b1     = (const float*)d_in[4];
    const float* W2     = (const float*)d_in[5];
    const float* Wt     = (const float*)d_in[6];
    float* out = (float*)d_out;

    // fused projections: rows = 2048 per input, tiles 64x64 -> grid (32,4,2)
    dim3 ggrid(2048 / 64, DD / 64, 2);
    gemm_nt_t<<<ggrid, 256>>>(x, memory, W1, W2, b1);

    const int smem_bytes = (DD * S1H_LD + DD * S2H_LD) * 2 + DD * 4 + TMK * 4;
    cudaFuncSetAttribute(attn_kernel,
                         cudaFuncAttributeMaxDynamicSharedMemorySize, smem_bytes);
    dim3 agrid(LXN / TXK, LMN / TMK, BB);
    attn_kernel<<<agrid, 256, smem_bytes>>>(mask, Wt, out);
}

// round 4
// speedup vs baseline: 1.3038x; 1.0914x over previous
#include <cuda_runtime.h>
#include <cuda_fp16.h>

#define DD   256
#define BB   4
#define LXN  512
#define LMN  512

#define TXK  32      // x-rows per attn tile
#define TMK  64      // m-cols per attn tile
#define S1H_LD 40    // halves; 80B rows (16B aligned)
#define S2H_LD 72    // halves; 144B rows (16B aligned)

// Transposed half projections: [b][d][L]
__device__ __half g_item1t[BB * DD * LXN];
__device__ __half g_item2t[BB * DD * LMN];
// Compacted item2 (active m-columns only, padded to TMK multiple)
__device__ __half g_item2c[BB * DD * LMN];
__device__ int    g_midx[BB * LMN];
__device__ int    g_cnt[BB];

__device__ __forceinline__ __half2 htanh2(__half2 x) {
    unsigned u = *reinterpret_cast<unsigned*>(&x);
    unsigned r;
    asm("tanh.approx.f16x2 %0, %1;" : "=r"(r) : "r"(u));
    return *reinterpret_cast<__half2*>(&r);
}

// ---------------------------------------------------------------------------
// Output prefill: every element -10000 (masked default; attn overwrites active)
// ---------------------------------------------------------------------------
__global__ void fill_kernel(float4* __restrict__ out, int n4) {
    const float4 v = make_float4(-10000.f, -10000.f, -10000.f, -10000.f);
    for (int i = blockIdx.x * blockDim.x + threadIdx.x; i < n4;
         i += gridDim.x * blockDim.x)
        out[i] = v;
}

// ---------------------------------------------------------------------------
// Stable mask compaction: one CTA per batch, 512 threads, warp-ballot scan.
// g_midx[b][0..n) = sorted active m indices; padded to TMK multiple with the
// last active index (duplicate compute, identical stores -> benign).
// ---------------------------------------------------------------------------
__global__ __launch_bounds__(LMN) void compact_mask(const int* __restrict__ mask) {
    const int b = blockIdx.x;
    const int t = threadIdx.x;
    const int lane = t & 31, w = t >> 5;

    int flag = mask[b * LMN + t] != 0;
    unsigned bal = __ballot_sync(0xffffffffu, flag);
    int pre = __popc(bal & ((1u << lane) - 1u));

    __shared__ int wcnt[16], woff[16], s_n;
    if (lane == 0) wcnt[w] = __popc(bal);
    __syncthreads();
    if (t == 0) {
        int s = 0;
        for (int i = 0; i < 16; ++i) { woff[i] = s; s += wcnt[i]; }
        s_n = s;
        g_cnt[b] = s;
    }
    __syncthreads();
    if (flag) g_midx[b * LMN + woff[w] + pre] = t;
    __syncthreads();   // make g_midx writes visible within block

    const int n = s_n;
    if (n > 0) {
        const int padded = (n + TMK - 1) / TMK * TMK;
        if (t >= n && t < padded)
            g_midx[b * LMN + t] = g_midx[b * LMN + n - 1];
    }
}

// ---------------------------------------------------------------------------
// Gather compacted item2 columns: g_item2c[b][d][j] = g_item2t[b][d][midx[j]]
// ---------------------------------------------------------------------------
__global__ __launch_bounds__(128) void gather_item2() {
    const int d = blockIdx.x;
    const int b = blockIdx.y;
    const int n = g_cnt[b];
    const int padded = (n + TMK - 1) / TMK * TMK;
    const __half* src = g_item2t + (b * DD + d) * LMN;
    __half*       dst = g_item2c + (b * DD + d) * LMN;
    const int* mi = g_midx + b * LMN;
    for (int j = threadIdx.x; j < padded; j += 128)
        dst[j] = src[mi[j]];
}

// ---------------------------------------------------------------------------
// Fused NT-GEMM pair: out_t[b][d][l] = half( sum_k A[b,l,k]*W[d,k] (+ bias[d]) )
// ---------------------------------------------------------------------------
__global__ __launch_bounds__(256) void gemm_nt_t(const float* __restrict__ Xin,
                                                 const float* __restrict__ Min,
                                                 const float* __restrict__ W1,
                                                 const float* __restrict__ W2,
                                                 const float* __restrict__ b1) {
    __shared__ float As[16][68];
    __shared__ float Ws[16][68];

    const int which = blockIdx.z;
    const float* A = which ? Min : Xin;
    const float* W = which ? W2  : W1;
    __half* out    = which ? g_item2t : g_item1t;

    const int tid = threadIdx.x;
    const int m0 = blockIdx.x * 64;     // row tile (b*L + l)
    const int n0 = blockIdx.y * 64;     // d tile
    const int tx = tid & 15;
    const int ty = tid >> 4;
    const int lr = tid >> 2;
    const int lk = (tid & 3) << 2;

    float acc[4][4] = {};

    for (int k0 = 0; k0 < DD; k0 += 16) {
        float4 av = *(const float4*)&A[(m0 + lr) * DD + k0 + lk];
        float4 wv = *(const float4*)&W[(n0 + lr) * DD + k0 + lk];
        __syncthreads();
        As[lk + 0][lr] = av.x; As[lk + 1][lr] = av.y;
        As[lk + 2][lr] = av.z; As[lk + 3][lr] = av.w;
        Ws[lk + 0][lr] = wv.x; Ws[lk + 1][lr] = wv.y;
        Ws[lk + 2][lr] = wv.z; Ws[lk + 3][lr] = wv.w;
        __syncthreads();

        #pragma unroll
        for (int k = 0; k < 16; ++k) {
            float4 a4 = *(const float4*)&As[k][tx * 4];
            float4 w4 = *(const float4*)&Ws[k][ty * 4];
            float ar[4] = {a4.x, a4.y, a4.z, a4.w};
            float wr[4] = {w4.x, w4.y, w4.z, w4.w};
            #pragma unroll
            for (int i = 0; i < 4; ++i)
                #pragma unroll
                for (int j = 0; j < 4; ++j)
                    acc[i][j] += ar[i] * wr[j];
        }
    }

    const int r_base = m0 + tx * 4;
    const int bb = r_base >> 9;
    const int lb = r_base & 511;

    float4 bv = make_float4(0.f, 0.f, 0.f, 0.f);
    if (!which) bv = *(const float4*)&b1[n0 + ty * 4];
    float bj[4] = {bv.x, bv.y, bv.z, bv.w};

    #pragma unroll
    for (int j = 0; j < 4; ++j) {
        int d = n0 + ty * 4 + j;
        __half2 p0 = __halves2half2(__float2half_rn(acc[0][j] + bj[j]),
                                    __float2half_rn(acc[1][j] + bj[j]));
        __half2 p1 = __halves2half2(__float2half_rn(acc[2][j] + bj[j]),
                                    __float2half_rn(acc[3][j] + bj[j]));
        uint2 u;
        u.x = *reinterpret_cast<unsigned*>(&p0);
        u.y = *reinterpret_cast<unsigned*>(&p1);
        *(uint2*)&out[((bb * DD + d) * 512) + lb] = u;
    }
}

// ---------------------------------------------------------------------------
// attn over ACTIVE m-columns only. Tile 32x x 64(active)m. f16x2 core,
// fp32 re-accumulate every 64 d. Scatter-store via g_midx.
// ---------------------------------------------------------------------------
extern __shared__ __align__(16) char smem_raw[];

__global__ __launch_bounds__(256) void attn_kernel(const float* __restrict__ Wt,
                                                   float* __restrict__ out) {
    const int b  = blockIdx.z;
    const int m0 = blockIdx.y * TMK;
    const int n_act = g_cnt[b];
    if (m0 >= n_act) return;

    __half*   s1   = (__half*)smem_raw;               // [DD][S1H_LD]
    __half*   s2   = s1 + DD * S1H_LD;                // [DD][S2H_LD]
    unsigned* swt  = (unsigned*)(s2 + DD * S2H_LD);   // [DD] half2 splat

    const int tid = threadIdx.x;
    const int x0 = blockIdx.x * TXK;

    {
        const int d = tid;
        const float4* p1 = (const float4*)(g_item1t + (b * DD + d) * LXN + x0);
        float4* q1 = (float4*)(s1 + d * S1H_LD);
        #pragma unroll
        for (int j = 0; j < 4; ++j) q1[j] = p1[j];           // 32 halves
        const float4* p2 = (const float4*)(g_item2c + (b * DD + d) * LMN + m0);
        float4* q2 = (float4*)(s2 + d * S2H_LD);
        #pragma unroll
        for (int j = 0; j < 8; ++j) q2[j] = p2[j];           // 64 halves
        __half h = __float2half_rn(Wt[d]);
        __half2 hh = __halves2half2(h, h);
        swt[d] = *reinterpret_cast<unsigned*>(&hh);
    }
    __syncthreads();

    const int tx = tid & 15;    // x pair
    const int tm = tid >> 4;    // m quad
    const __half* s1p = s1 + tx * 2;
    const __half* s2p = s2 + tm * 4;

    const __half2 hz = __halves2half2(__ushort_as_half(0), __ushort_as_half(0));
    float2 f00 = {0.f, 0.f}, f01 = {0.f, 0.f}, f10 = {0.f, 0.f}, f11 = {0.f, 0.f};

    #pragma unroll 1
    for (int d0 = 0; d0 < DD; d0 += 64) {
        __half2 a00 = hz, a01 = hz, a10 = hz, a11 = hz;
        #pragma unroll 8
        for (int d = d0; d < d0 + 64; ++d) {
            __half2 a = *(const __half2*)(s1p + d * S1H_LD);      // 2 x-vals
            uint2 mv  = *(const uint2*)(s2p + d * S2H_LD);        // 4 m-vals
            __half2 m01 = *reinterpret_cast<__half2*>(&mv.x);
            __half2 m23 = *reinterpret_cast<__half2*>(&mv.y);
            unsigned wu = swt[d];
            __half2 wt2 = *reinterpret_cast<__half2*>(&wu);
            __half2 aa0 = __low2half2(a);
            __half2 aa1 = __high2half2(a);
            a00 = __hfma2(htanh2(__hadd2(aa0, m01)), wt2, a00);
            a01 = __hfma2(htanh2(__hadd2(aa0, m23)), wt2, a01);
            a10 = __hfma2(htanh2(__hadd2(aa1, m01)), wt2, a10);
            a11 = __hfma2(htanh2(__hadd2(aa1, m23)), wt2, a11);
        }
        float2 t;
        t = __half22float2(a00); f00.x += t.x; f00.y += t.y;
        t = __half22float2(a01); f01.x += t.x; f01.y += t.y;
        t = __half22float2(a10); f10.x += t.x; f10.y += t.y;
        t = __half22float2(a11); f11.x += t.x; f11.y += t.y;
    }

    // scatter-store to true m positions (padded lanes duplicate the last
    // active column: identical values to identical addresses -> benign)
    int4 mi = *(const int4*)&g_midx[b * LMN + m0 + tm * 4];
    const int x = x0 + tx * 2;
    float* r0 = out + (b * LXN + x) * (long)LMN;
    float* r1 = r0 + LMN;
    r0[mi.x] = f00.x; r0[mi.y] = f00.y; r0[mi.z] = f01.x; r0[mi.w] = f01.y;
    r1[mi.x] = f10.x; r1[mi.y] = f10.y; r1[mi.z] = f11.x; r1[mi.w] = f11.y;
}

// ---------------------------------------------------------------------------

extern "C" void kernel_launch(void* const* d_in, const int* in_sizes, int n_in,
                              void* d_out, int out_size) {
    const float* x      = (const float*)d_in[0];
    const float* memory = (const float*)d_in[1];
    const int*   mask   = (const int*)d_in[2];
    const float* W1     = (const float*)d_in[3];
    const float* b1     = (const float*)d_in[4];
    const float* W2     = (const float*)d_in[5];
    const float* Wt     = (const float*)d_in[6];
    float* out = (float*)d_out;

    // 1) prefill output with -10000
    fill_kernel<<<1024, 256>>>((float4*)out, out_size / 4);

    // 2) mask compaction (per batch)
    compact_mask<<<BB, LMN>>>(mask);

    // 3) fused projections
    dim3 ggrid(2048 / 64, DD / 64, 2);
    gemm_nt_t<<<ggrid, 256>>>(x, memory, W1, W2, b1);

    // 4) gather active item2 columns into compacted buffer
    dim3 ugrid(DD, BB);
    gather_item2<<<ugrid, 128>>>();

    // 5) attention over active columns only
    const int smem_bytes = (DD * S1H_LD + DD * S2H_LD) * 2 + DD * 4;
    cudaFuncSetAttribute(attn_kernel,
                         cudaFuncAttributeMaxDynamicSharedMemorySize, smem_bytes);
    dim3 agrid(LXN / TXK, LMN / TMK, BB);
    attn_kernel<<<agrid, 256, smem_bytes>>>(Wt, out);
}

// round 5
// speedup vs baseline: 1.3802x; 1.0585x over previous
#include <cuda_runtime.h>
#include <cuda_fp16.h>

#define DD   256
#define BB   4
#define LXN  512
#define LMN  512

#define TXK  32      // x-rows per attn tile
#define TMK  64      // m-cols per attn tile
#define S1H_LD 40    // halves; 80B rows (16B aligned)
#define S2H_LD 72    // halves; 144B rows (16B aligned)

// Transposed half projections: [b][d][L]
__device__ __half g_item1t[BB * DD * LXN];
// item2 written directly compacted by the GEMM epilogue: [b][d][pos]
__device__ __half g_item2c[BB * DD * LMN];
__device__ int    g_midx[BB * LMN];   // compacted -> original m index
__device__ int    g_pos [BB * LMN];   // original m -> compacted pos (-1 inactive)
__device__ int    g_cnt [BB];

__device__ __forceinline__ __half2 htanh2(__half2 x) {
    unsigned u = *reinterpret_cast<unsigned*>(&x);
    unsigned r;
    asm("tanh.approx.f16x2 %0, %1;" : "=r"(r) : "r"(u));
    return *reinterpret_cast<__half2*>(&r);
}

// ---------------------------------------------------------------------------
// prep: blocks 0..BB-1 do stable mask compaction (one CTA per batch);
// remaining blocks fill the output with -10000.
// ---------------------------------------------------------------------------
__global__ __launch_bounds__(512) void prep_kernel(const int* __restrict__ mask,
                                                   float4* __restrict__ out,
                                                   int n4) {
    if (blockIdx.x < BB) {
        const int b = blockIdx.x;
        const int t = threadIdx.x;
        const int lane = t & 31, w = t >> 5;

        int flag = mask[b * LMN + t] != 0;
        unsigned bal = __ballot_sync(0xffffffffu, flag);
        int pre = __popc(bal & ((1u << lane) - 1u));

        __shared__ int wcnt[16], woff[16], s_n;
        if (lane == 0) wcnt[w] = __popc(bal);
        __syncthreads();
        if (t == 0) {
            int s = 0;
            for (int i = 0; i < 16; ++i) { woff[i] = s; s += wcnt[i]; }
            s_n = s;
            g_cnt[b] = s;
        }
        __syncthreads();
        int p = woff[w] + pre;
        g_pos[b * LMN + t] = flag ? p : -1;
        if (flag) g_midx[b * LMN + p] = t;
        __syncthreads();

        const int n = s_n;
        if (n > 0) {
            const int padded = (n + TMK - 1) / TMK * TMK;
            if (t >= n && t < padded)
                g_midx[b * LMN + t] = g_midx[b * LMN + n - 1];
        }
    } else {
        const float4 v = make_float4(-10000.f, -10000.f, -10000.f, -10000.f);
        const int stride = (gridDim.x - BB) * blockDim.x;
        for (int i = (blockIdx.x - BB) * blockDim.x + threadIdx.x; i < n4;
             i += stride)
            out[i] = v;
    }
}

// ---------------------------------------------------------------------------
// Fused NT-GEMM pair, HFMA2 core (half2 SIMD along k, fp32 flush every 64 k).
// which==0: x*W1^T + b1 -> g_item1t, dense transposed [b][d][l] half store.
// which==1: mem*W2^T    -> g_item2c, scatter to compacted column g_pos[l].
// Tile 64 rows x 64 d, BK=32, 256 threads, 4x4 microtile.
// ---------------------------------------------------------------------------
__global__ __launch_bounds__(256) void gemm_h(const float* __restrict__ Xin,
                                              const float* __restrict__ Min,
                                              const float* __restrict__ W1,
                                              const float* __restrict__ W2,
                                              const float* __restrict__ b1) {
    __shared__ __half2 As2[16][76];
    __shared__ __half2 Ws2[16][76];

    const int which = blockIdx.z;
    const float* A = which ? Min : Xin;
    const float* W = which ? W2  : W1;

    const int tid = threadIdx.x;
    const int m0 = blockIdx.x * 64;     // row tile (b*L + l)
    const int n0 = blockIdx.y * 64;     // d tile
    const int tx = tid & 15;
    const int ty = tid >> 4;
    const int lr = tid >> 2;            // load row 0..63
    const int lk = (tid & 3) * 8;       // load k offset {0,8,16,24}

    float accf[4][4] = {};
    const __half2 hz = __float2half2_rn(0.f);

    for (int k0 = 0; k0 < DD; k0 += 64) {
        __half2 acc2[4][4];
        #pragma unroll
        for (int i = 0; i < 4; ++i)
            #pragma unroll
            for (int j = 0; j < 4; ++j) acc2[i][j] = hz;

        #pragma unroll
        for (int kk = 0; kk < 64; kk += 32) {
            const int kb = k0 + kk;
            float4 a0 = *(const float4*)&A[(m0 + lr) * DD + kb + lk];
            float4 a1 = *(const float4*)&A[(m0 + lr) * DD + kb + lk + 4];
            float4 w0 = *(const float4*)&W[(n0 + lr) * DD + kb + lk];
            float4 w1 = *(const float4*)&W[(n0 + lr) * DD + kb + lk + 4];
            __syncthreads();
            {
                const int c2 = lk >> 1;   // half2 column base {0,4,8,12}
                As2[c2 + 0][lr] = __floats2half2_rn(a0.x, a0.y);
                As2[c2 + 1][lr] = __floats2half2_rn(a0.z, a0.w);
                As2[c2 + 2][lr] = __floats2half2_rn(a1.x, a1.y);
                As2[c2 + 3][lr] = __floats2half2_rn(a1.z, a1.w);
                Ws2[c2 + 0][lr] = __floats2half2_rn(w0.x, w0.y);
                Ws2[c2 + 1][lr] = __floats2half2_rn(w0.z, w0.w);
                Ws2[c2 + 2][lr] = __floats2half2_rn(w1.x, w1.y);
                Ws2[c2 + 3][lr] = __floats2half2_rn(w1.z, w1.w);
            }
            __syncthreads();

            #pragma unroll
            for (int k2 = 0; k2 < 16; ++k2) {
                uint2 au = *(const uint2*)&As2[k2][tx * 4];
                uint2 au2 = *(const uint2*)&As2[k2][tx * 4 + 2];
                uint2 wu = *(const uint2*)&Ws2[k2][ty * 4];
                uint2 wu2 = *(const uint2*)&Ws2[k2][ty * 4 + 2];
                __half2 ar[4], wr[4];
                ar[0] = *reinterpret_cast<__half2*>(&au.x);
                ar[1] = *reinterpret_cast<__half2*>(&au.y);
                ar[2] = *reinterpret_cast<__half2*>(&au2.x);
                ar[3] = *reinterpret_cast<__half2*>(&au2.y);
                wr[0] = *reinterpret_cast<__half2*>(&wu.x);
                wr[1] = *reinterpret_cast<__half2*>(&wu.y);
                wr[2] = *reinterpret_cast<__half2*>(&wu2.x);
                wr[3] = *reinterpret_cast<__half2*>(&wu2.y);
                #pragma unroll
                for (int i = 0; i < 4; ++i)
                    #pragma unroll
                    for (int j = 0; j < 4; ++j)
                        acc2[i][j] = __hfma2(ar[i], wr[j], acc2[i][j]);
            }
        }
        // fp32 flush
        #pragma unroll
        for (int i = 0; i < 4; ++i)
            #pragma unroll
            for (int j = 0; j < 4; ++j) {
                float2 t = __half22float2(acc2[i][j]);
                accf[i][j] += t.x + t.y;
            }
    }

    const int r_base = m0 + tx * 4;
    const int bb = r_base >> 9;          // batch (rows never cross: 512%64==0)
    const int lb = r_base & 511;

    if (!which) {
        float4 bv = *(const float4*)&b1[n0 + ty * 4];
        float bj[4] = {bv.x, bv.y, bv.z, bv.w};
        #pragma unroll
        for (int j = 0; j < 4; ++j) {
            int d = n0 + ty * 4 + j;
            __half2 p0 = __halves2half2(__float2half_rn(accf[0][j] + bj[j]),
                                        __float2half_rn(accf[1][j] + bj[j]));
            __half2 p1 = __halves2half2(__float2half_rn(accf[2][j] + bj[j]),
                                        __float2half_rn(accf[3][j] + bj[j]));
            uint2 u;
            u.x = *reinterpret_cast<unsigned*>(&p0);
            u.y = *reinterpret_cast<unsigned*>(&p1);
            *(uint2*)&g_item1t[((bb * DD + d) * LXN) + lb] = u;
        }
    } else {
        int4 pi = *(const int4*)&g_pos[bb * LMN + lb];
        int pos[4] = {pi.x, pi.y, pi.z, pi.w};
        #pragma unroll
        for (int j = 0; j < 4; ++j) {
            int d = n0 + ty * 4 + j;
            __half* dst = g_item2c + (bb * DD + d) * LMN;
            #pragma unroll
            for (int i = 0; i < 4; ++i)
                if (pos[i] >= 0)
                    dst[pos[i]] = __float2half_rn(accf[i][j]);
        }
    }
}

// ---------------------------------------------------------------------------
// attn over ACTIVE m-columns only. Tile 32x x 64m(active), f16x2 core,
// fp32 re-accumulate every 64 d. Scatter-store via g_midx.
// ---------------------------------------------------------------------------
extern __shared__ __align__(16) char smem_raw[];

__global__ __launch_bounds__(256) void attn_kernel(const float* __restrict__ Wt,
                                                   float* __restrict__ out) {
    const int b  = blockIdx.z;
    const int m0 = blockIdx.y * TMK;
    const int n_act = g_cnt[b];
    if (m0 >= n_act) return;

    __half*   s1   = (__half*)smem_raw;               // [DD][S1H_LD]
    __half*   s2   = s1 + DD * S1H_LD;                // [DD][S2H_LD]
    unsigned* swt  = (unsigned*)(s2 + DD * S2H_LD);   // [DD] half2 splat

    const int tid = threadIdx.x;
    const int x0 = blockIdx.x * TXK;

    {
        const int d = tid;
        const float4* p1 = (const float4*)(g_item1t + (b * DD + d) * LXN + x0);
        float4* q1 = (float4*)(s1 + d * S1H_LD);
        #pragma unroll
        for (int j = 0; j < 4; ++j) q1[j] = p1[j];           // 32 halves

        const __half* src2 = g_item2c + (b * DD + d) * LMN;
        if (m0 + TMK <= n_act) {                              // full tile: bulk
            const float4* p2 = (const float4*)(src2 + m0);
            float4* q2 = (float4*)(s2 + d * S2H_LD);
            #pragma unroll
            for (int j = 0; j < 8; ++j) q2[j] = p2[j];        // 64 halves
        } else {                                              // tail: clamped
            #pragma unroll 8
            for (int j = 0; j < TMK; ++j) {
                int jj = m0 + j;
                if (jj >= n_act) jj = n_act - 1;
                s2[d * S2H_LD + j] = src2[jj];
            }
        }
        __half h = __float2half_rn(Wt[d]);
        __half2 hh = __halves2half2(h, h);
        swt[d] = *reinterpret_cast<unsigned*>(&hh);
    }
    __syncthreads();

    const int tx = tid & 15;    // x pair
    const int tm = tid >> 4;    // m quad
    const __half* s1p = s1 + tx * 2;
    const __half* s2p = s2 + tm * 4;

    const __half2 hz = __float2half2_rn(0.f);
    float2 f00 = {0.f, 0.f}, f01 = {0.f, 0.f}, f10 = {0.f, 0.f}, f11 = {0.f, 0.f};

    #pragma unroll 1
    for (int d0 = 0; d0 < DD; d0 += 64) {
        __half2 a00 = hz, a01 = hz, a10 = hz, a11 = hz;
        #pragma unroll 8
        for (int d = d0; d < d0 + 64; ++d) {
            __half2 a = *(const __half2*)(s1p + d * S1H_LD);      // 2 x-vals
            uint2 mv  = *(const uint2*)(s2p + d * S2H_LD);        // 4 m-vals
            __half2 m01 = *reinterpret_cast<__half2*>(&mv.x);
            __half2 m23 = *reinterpret_cast<__half2*>(&mv.y);
            unsigned wu = swt[d];
            __half2 wt2 = *reinterpret_cast<__half2*>(&wu);
            __half2 aa0 = __low2half2(a);
            __half2 aa1 = __high2half2(a);
            a00 = __hfma2(htanh2(__hadd2(aa0, m01)), wt2, a00);
            a01 = __hfma2(htanh2(__hadd2(aa0, m23)), wt2, a01);
            a10 = __hfma2(htanh2(__hadd2(aa1, m01)), wt2, a10);
            a11 = __hfma2(htanh2(__hadd2(aa1, m23)), wt2, a11);
        }
        float2 t;
        t = __half22float2(a00); f00.x += t.x; f00.y += t.y;
        t = __half22float2(a01); f01.x += t.x; f01.y += t.y;
        t = __half22float2(a10); f10.x += t.x; f10.y += t.y;
        t = __half22float2(a11); f11.x += t.x; f11.y += t.y;
    }

    // scatter-store (padded lanes duplicate the last active column: identical
    // values to identical addresses -> benign)
    int4 mi = *(const int4*)&g_midx[b * LMN + m0 + tm * 4];
    const int x = x0 + tx * 2;
    float* r0 = out + (b * LXN + x) * (long)LMN;
    float* r1 = r0 + LMN;
    r0[mi.x] = f00.x; r0[mi.y] = f00.y; r0[mi.z] = f01.x; r0[mi.w] = f01.y;
    r1[mi.x] = f10.x; r1[mi.y] = f10.y; r1[mi.z] = f11.x; r1[mi.w] = f11.y;
}

// ---------------------------------------------------------------------------

extern "C" void kernel_launch(void* const* d_in, const int* in_sizes, int n_in,
                              void* d_out, int out_size) {
    const float* x      = (const float*)d_in[0];
    const float* memory = (const float*)d_in[1];
    const int*   mask   = (const int*)d_in[2];
    const float* W1     = (const float*)d_in[3];
    const float* b1     = (const float*)d_in[4];
    const float* W2     = (const float*)d_in[5];
    const float* Wt     = (const float*)d_in[6];
    float* out = (float*)d_out;

    // 1) compact mask + prefill output (-10000) in one launch
    prep_kernel<<<BB + 508, 512>>>(mask, (float4*)out, out_size / 4);

    // 2) fused half2 projections (item2 scatters into compacted layout)
    dim3 ggrid(2048 / 64, DD / 64, 2);
    gemm_h<<<ggrid, 256>>>(x, memory, W1, W2, b1);

    // 3) attention over active columns only
    const int smem_bytes = (DD * S1H_LD + DD * S2H_LD) * 2 + DD * 4;
    cudaFuncSetAttribute(attn_kernel,
                         cudaFuncAttributeMaxDynamicSharedMemorySize, smem_bytes);
    dim3 agrid(LXN / TXK, LMN / TMK, BB);
    attn_kernel<<<agrid, 256, smem_bytes>>>(Wt, out);
}